// round 2
// baseline (speedup 1.0000x reference)
#include <cuda_runtime.h>

#define NMAX   1000000
#define NCELLS 220000
#define GX 220
#define GY 250

// -------------------- static scratch (allocation-free rule) --------------------
static __device__ int   d_key[NMAX];
static __device__ int   d_ipos[NMAX];
static __device__ int   d_pvid[NMAX];
static __device__ int   d_cnt[NCELLS];
static __device__ int   d_cursor[NCELLS];
static __device__ int   d_cellvid[NCELLS];
static __device__ int   d_cellstart[NCELLS];
static __device__ float d_sums[NCELLS * 3];
static __device__ float d_mean[NCELLS * 3];
static __device__ int   d_voxstart[NCELLS];
static __device__ int   d_voxcnt[NCELLS];
static __device__ float d_y0[(size_t)NMAX * 32];     // layer0 pre-act, then in-place post-BN-ReLU
static __device__ float d_xmax[(size_t)NCELLS * 32];
static __device__ float d_h[(size_t)NMAX * 128];     // layer1 pre-act
static __device__ float d_stats0[64];
static __device__ float d_stats1[256];
static __device__ float d_bn0[64];                   // [scale(32) | shift(32)]
static __device__ float d_bn1[256];                  // [scale(128) | shift(128)]
static __device__ unsigned long long d_bsum[256];
static __device__ int   d_meta[2];                   // [0]=V (num voxels), [1]=Nvalid

// Exact IEEE voxel coords (match jnp float32 sub/div/floor bit-for-bit)
__device__ __forceinline__ int3 coordsOf(float x, float y, float z) {
    int ix = (int)floorf(__fdiv_rn(x, 0.32f));
    int iy = (int)floorf(__fdiv_rn(__fadd_rn(y, 40.0f), 0.32f));
    int iz = (int)floorf(__fdiv_rn(__fadd_rn(z, 3.0f), 4.0f));
    return make_int3(ix, iy, iz);
}

// -------------------- K0: zero per-launch state --------------------
__global__ void k_zero() {
    int i = blockIdx.x * blockDim.x + threadIdx.x;
    if (i < NCELLS) {
        d_cnt[i] = 0; d_cursor[i] = 0;
        d_sums[i * 3 + 0] = 0.f; d_sums[i * 3 + 1] = 0.f; d_sums[i * 3 + 2] = 0.f;
    }
    if (i < 64)  d_stats0[i] = 0.f;
    if (i < 256) d_stats1[i] = 0.f;
}

// -------------------- K1: keys + histogram + xyz sums --------------------
__global__ void k_points(const float* __restrict__ pts, int n) {
    int i = blockIdx.x * blockDim.x + threadIdx.x;
    if (i >= n) return;
    const float* p = pts + (size_t)i * 5;
    float b = p[0], x = p[1], y = p[2], z = p[3];
    int3 c = coordsOf(x, y, z);
    int key = -1;
    if (c.x >= 0 && c.x < GX && c.y >= 0 && c.y < GY && c.z == 0) {
        key = (int)b * 55000 + c.x * 250 + c.y + c.z;
        if (key < 0 || key >= NCELLS) key = -1;
    }
    d_key[i] = key;
    if (key >= 0) {
        atomicAdd(&d_cnt[key], 1);
        atomicAdd(&d_sums[key * 3 + 0], x);
        atomicAdd(&d_sums[key * 3 + 1], y);
        atomicAdd(&d_sums[key * 3 + 2], z);
    }
}

// -------------------- K2: packed scan (hi: occupancy -> vid, lo: count -> point start) ------
__global__ void k_scan1() {
    __shared__ unsigned long long s[1024];
    int tid = threadIdx.x;
    int c = blockIdx.x * 1024 + tid;
    unsigned long long v = 0ULL;
    if (c < NCELLS) {
        int cn = d_cnt[c];
        v = ((unsigned long long)(cn > 0) << 32) | (unsigned int)cn;
    }
    s[tid] = v;
    __syncthreads();
    for (int o = 1; o < 1024; o <<= 1) {
        unsigned long long t = (tid >= o) ? s[tid - o] : 0ULL;
        __syncthreads();
        s[tid] += t;
        __syncthreads();
    }
    unsigned long long exc = s[tid] - v;
    if (c < NCELLS) {
        d_cellvid[c]   = (int)(exc >> 32);
        d_cellstart[c] = (int)(exc & 0xffffffffULL);
    }
    if (tid == 1023) d_bsum[blockIdx.x] = s[1023];
}

__global__ void k_scan2(int nb) {
    if (threadIdx.x == 0) {
        unsigned long long run = 0ULL;
        for (int i = 0; i < nb; i++) {
            unsigned long long t = d_bsum[i];
            d_bsum[i] = run;
            run += t;
        }
        d_meta[0] = (int)(run >> 32);
        d_meta[1] = (int)(run & 0xffffffffULL);
    }
}

// -------------------- K3: finalize cells, voxel meta, means, coords output ---------
__global__ void k_cells(float* __restrict__ out, int Vh) {
    int c = blockIdx.x * blockDim.x + threadIdx.x;
    if (c >= NCELLS) return;
    unsigned long long off = d_bsum[c >> 10];
    int vid = d_cellvid[c]   + (int)(off >> 32);
    int cst = d_cellstart[c] + (int)(off & 0xffffffffULL);
    d_cellvid[c] = vid;
    d_cellstart[c] = cst;
    int cn = d_cnt[c];
    if (cn > 0) {
        d_voxstart[vid] = cst;
        d_voxcnt[vid]   = cn;
        float fn = (float)cn;
        d_mean[vid * 3 + 0] = d_sums[c * 3 + 0] / fn;
        d_mean[vid * 3 + 1] = d_sums[c * 3 + 1] / fn;
        d_mean[vid * 3 + 2] = d_sums[c * 3 + 2] / fn;
        if (vid < Vh) {
            int b = c / 55000; int rem = c - b * 55000;
            int cx = rem / 250; int cy = rem - cx * 250;
            float* oc = out + (size_t)Vh * 128 + (size_t)vid * 4;
            oc[0] = (float)b; oc[1] = 0.f; oc[2] = (float)cy; oc[3] = (float)cx;
        }
    }
}

// -------------------- K4: counting-sort scatter --------------------
__global__ void k_scatter(int n) {
    int i = blockIdx.x * blockDim.x + threadIdx.x;
    if (i >= n) return;
    int k = d_key[i];
    if (k >= 0) {
        int pos = d_cellstart[k] + atomicAdd(&d_cursor[k], 1);
        d_ipos[i] = pos;
        d_pvid[pos] = d_cellvid[k];
    } else {
        d_ipos[i] = -1;
    }
}

// -------------------- K5: layer0 matmul (10x32), y0 stored grouped-by-voxel --------
__global__ void k_l0(const float* __restrict__ pts, const float* __restrict__ w0, int n) {
    __shared__ float w0s[320];
    for (int j = threadIdx.x; j < 320; j += blockDim.x) w0s[j] = w0[j];
    __syncthreads();
    int i = blockIdx.x * blockDim.x + threadIdx.x;
    if (i >= n) return;
    int k = d_key[i];
    if (k < 0) return;
    const float* p = pts + (size_t)i * 5;
    float x = p[1], y = p[2], z = p[3], it = p[4];
    int3 c = coordsOf(x, y, z);
    int v = d_cellvid[k];
    const float XO = (float)(0.32 / 2 + 0.0);
    const float YO = (float)(0.32 / 2 - 40.0);
    const float ZO = (float)(4.0 / 2 - 3.0);
    float f[10];
    f[0] = x; f[1] = y; f[2] = z; f[3] = it;
    f[4] = x - d_mean[v * 3 + 0];
    f[5] = y - d_mean[v * 3 + 1];
    f[6] = z - d_mean[v * 3 + 2];
    f[7] = x - ((float)c.x * 0.32f + XO);
    f[8] = y - ((float)c.y * 0.32f + YO);
    f[9] = z - ZO;
    float acc[32];
#pragma unroll
    for (int cc = 0; cc < 32; cc++) acc[cc] = 0.f;
#pragma unroll
    for (int kk = 0; kk < 10; kk++) {
        float fv = f[kk];
#pragma unroll
        for (int cc = 0; cc < 32; cc++) acc[cc] = fmaf(fv, w0s[kk * 32 + cc], acc[cc]);
    }
    int pp = d_ipos[i];
    float4* dst = (float4*)(d_y0 + (size_t)pp * 32);
#pragma unroll
    for (int j = 0; j < 8; j++)
        dst[j] = make_float4(acc[4 * j], acc[4 * j + 1], acc[4 * j + 2], acc[4 * j + 3]);
}

// -------------------- K6: BN0 stats (sum, sumsq over all points, 32 ch) -----------
__global__ void k_stats32() {
    __shared__ float sh[2][8][32];
    int t = threadIdx.x;
    int ch = t & 31, rl = t >> 5;
    int NV = d_meta[1];
    float s = 0.f, ss = 0.f;
    for (int r = blockIdx.x * 8 + rl; r < NV; r += gridDim.x * 8) {
        float v = d_y0[(size_t)r * 32 + ch];
        s += v; ss += v * v;
    }
    sh[0][rl][ch] = s; sh[1][rl][ch] = ss;
    __syncthreads();
    if (t < 32) {
        float a = 0.f, b = 0.f;
#pragma unroll
        for (int j = 0; j < 8; j++) { a += sh[0][j][t]; b += sh[1][j][t]; }
        atomicAdd(&d_stats0[t], a);
        atomicAdd(&d_stats0[32 + t], b);
    }
}

__global__ void k_bnfin0(const float* __restrict__ g, const float* __restrict__ b) {
    int t = threadIdx.x;
    if (t >= 32) return;
    float n = (float)d_meta[1];
    float mu = d_stats0[t] / n;
    float var = d_stats0[32 + t] / n - mu * mu;
    float istd = 1.0f / sqrtf(var + 1e-3f);
    float sc = g[t] * istd;
    d_bn0[t] = sc;
    d_bn0[32 + t] = b[t] - mu * sc;
}

// -------------------- K7: BN0+ReLU in place + per-voxel xmax (warp per voxel) -----
__global__ void k_l0post() {
    int gw = (blockIdx.x * blockDim.x + threadIdx.x) >> 5;
    int lane = threadIdx.x & 31;
    if (gw >= d_meta[0]) return;
    float sc = d_bn0[lane], sh = d_bn0[32 + lane];
    int st = d_voxstart[gw], en = st + d_voxcnt[gw];
    float m = 0.f;
    for (int p = st; p < en; p++) {
        float vv = d_y0[(size_t)p * 32 + lane];
        float xr = fmaxf(fmaf(vv, sc, sh), 0.f);
        d_y0[(size_t)p * 32 + lane] = xr;
        m = fmaxf(m, xr);
    }
    d_xmax[(size_t)gw * 32 + lane] = m;
}

// -------------------- K8: layer1 GEMM 1M x (64 -> 128), packed f32x2 FMA ----------
__global__ void __launch_bounds__(256) k_l1(const float* __restrict__ w1) {
    __shared__ float4 w1s[2048];                       // 64x128 f32 = 32KB
    const float4* wv = (const float4*)w1;
    for (int j = threadIdx.x; j < 2048; j += 256) w1s[j] = wv[j];
    __syncthreads();
    int p = blockIdx.x * 256 + threadIdx.x;
    if (p >= d_meta[1]) return;
    float xc[64];
    const float4* a = (const float4*)(d_y0 + (size_t)p * 32);
#pragma unroll
    for (int j = 0; j < 8; j++) {
        float4 t = a[j];
        xc[4 * j] = t.x; xc[4 * j + 1] = t.y; xc[4 * j + 2] = t.z; xc[4 * j + 3] = t.w;
    }
    int v = d_pvid[p];
    const float4* mr = (const float4*)(d_xmax + (size_t)v * 32);
#pragma unroll
    for (int j = 0; j < 8; j++) {
        float4 t = mr[j];
        xc[32 + 4 * j] = t.x; xc[33 + 4 * j] = t.y; xc[34 + 4 * j] = t.z; xc[35 + 4 * j] = t.w;
    }
    const ulonglong2* ws = (const ulonglong2*)w1s;
    unsigned long long* hrow = (unsigned long long*)(d_h + (size_t)p * 128);
#pragma unroll 1
    for (int pass = 0; pass < 8; pass++) {             // 16 output channels per pass
        unsigned long long acc[8];
#pragma unroll
        for (int j = 0; j < 8; j++) acc[j] = 0ULL;     // two packed 0.0f
#pragma unroll 4
        for (int k = 0; k < 64; k++) {
            unsigned long long a2;
            asm("mov.b64 %0, {%1, %1};" : "=l"(a2) : "r"(__float_as_uint(xc[k])));
            const ulonglong2* row = ws + k * 32 + pass * 4;
#pragma unroll
            for (int j = 0; j < 4; j++) {
                ulonglong2 wp = row[j];
                asm("fma.rn.f32x2 %0, %1, %2, %0;" : "+l"(acc[2 * j])     : "l"(a2), "l"(wp.x));
                asm("fma.rn.f32x2 %0, %1, %2, %0;" : "+l"(acc[2 * j + 1]) : "l"(a2), "l"(wp.y));
            }
        }
#pragma unroll
        for (int j = 0; j < 8; j++) hrow[pass * 8 + j] = acc[j];
    }
}

// -------------------- K9: BN1 stats (128 ch) --------------------
__global__ void k_stats128() {
    __shared__ float sh[2][2][128];
    int t = threadIdx.x;
    int ch = t & 127, rl = t >> 7;
    int NV = d_meta[1];
    float s = 0.f, ss = 0.f;
    for (int r = blockIdx.x * 2 + rl; r < NV; r += gridDim.x * 2) {
        float v = d_h[(size_t)r * 128 + ch];
        s += v; ss += v * v;
    }
    sh[0][rl][ch] = s; sh[1][rl][ch] = ss;
    __syncthreads();
    if (t < 128) {
        atomicAdd(&d_stats1[t],       sh[0][0][t] + sh[0][1][t]);
        atomicAdd(&d_stats1[128 + t], sh[1][0][t] + sh[1][1][t]);
    }
}

__global__ void k_bnfin1(const float* __restrict__ g, const float* __restrict__ b) {
    int t = threadIdx.x;
    if (t >= 128) return;
    float n = (float)d_meta[1];
    float mu = d_stats1[t] / n;
    float var = d_stats1[128 + t] / n - mu * mu;
    float istd = 1.0f / sqrtf(var + 1e-3f);
    float sc = g[t] * istd;
    d_bn1[t] = sc;
    d_bn1[128 + t] = b[t] - mu * sc;
}

// -------------------- K10: BN1+ReLU + per-voxel max -> pillar_feat ---------------
__global__ void k_final(float* __restrict__ out, int Vh) {
    int gw = (blockIdx.x * blockDim.x + threadIdx.x) >> 5;
    int lane = threadIdx.x & 31;
    if (gw >= d_meta[0] || gw >= Vh) return;
    float sc[4], sh[4], m[4];
#pragma unroll
    for (int q = 0; q < 4; q++) {
        sc[q] = d_bn1[q * 32 + lane];
        sh[q] = d_bn1[128 + q * 32 + lane];
        m[q] = 0.f;                                    // relu output >= 0, every voxel nonempty
    }
    int st = d_voxstart[gw], en = st + d_voxcnt[gw];
    for (int p = st; p < en; p++) {
        const float* hr = d_h + (size_t)p * 128;
#pragma unroll
        for (int q = 0; q < 4; q++) {
            float vv = hr[q * 32 + lane];
            m[q] = fmaxf(m[q], fmaxf(fmaf(vv, sc[q], sh[q]), 0.f));
        }
    }
    float* o = out + (size_t)gw * 128;
#pragma unroll
    for (int q = 0; q < 4; q++) o[q * 32 + lane] = m[q];
}

// -------------------- host --------------------
extern "C" void kernel_launch(void* const* d_in, const int* in_sizes, int n_in,
                              void* d_out, int out_size) {
    const float* pts = (const float*)d_in[0];
    const float* w0  = (const float*)d_in[1];
    const float* g0  = (const float*)d_in[2];
    const float* b0  = (const float*)d_in[3];
    const float* w1  = (const float*)d_in[4];
    const float* g1  = (const float*)d_in[5];
    const float* b1  = (const float*)d_in[6];
    float* out = (float*)d_out;

    int n = in_sizes[0] / 5;
    if (n > NMAX) n = NMAX;
    int Vh = out_size / 132;                 // pillar_feat (V*128) + pillar_coords (V*4)
    int nb = (NCELLS + 1023) / 1024;

    k_zero   <<<(NCELLS + 255) / 256, 256>>>();
    k_points <<<(n + 255) / 256, 256>>>(pts, n);
    k_scan1  <<<nb, 1024>>>();
    k_scan2  <<<1, 32>>>(nb);
    k_cells  <<<(NCELLS + 255) / 256, 256>>>(out, Vh);
    k_scatter<<<(n + 255) / 256, 256>>>(n);
    k_l0     <<<(n + 255) / 256, 256>>>(pts, w0, n);
    k_stats32<<<1024, 256>>>();
    k_bnfin0 <<<1, 32>>>(g0, b0);
    k_l0post <<<(NCELLS + 7) / 8, 256>>>();
    k_l1     <<<(n + 255) / 256, 256>>>(w1);
    k_stats128<<<2048, 256>>>();
    k_bnfin1 <<<1, 128>>>(g1, b1);
    k_final  <<<(NCELLS + 7) / 8, 256>>>(out, Vh);
}

// round 3
// speedup vs baseline: 1.0501x; 1.0501x over previous
#include <cuda_runtime.h>

#define NMAX   1000000
#define NCELLS 220000
#define GX 220
#define GY 250

// -------------------- static scratch --------------------
static __device__ int    d_key[NMAX];
static __device__ int    d_ipos[NMAX];
static __device__ int    d_cnt[NCELLS];
static __device__ int    d_cursor[NCELLS];
static __device__ int    d_cellvid[NCELLS];
static __device__ int    d_cellstart[NCELLS];
static __device__ float  d_sums[NCELLS * 3];
static __device__ float  d_mean[NCELLS * 3];
static __device__ int    d_voxstart[NCELLS];
static __device__ int    d_voxcnt[NCELLS];
static __device__ __align__(16) float d_feat[(size_t)NMAX * 12];
static __device__ __align__(16) float d_x[(size_t)NMAX * 32];
static __device__ __align__(16) float d_xmax[(size_t)NCELLS * 32];
static __device__ __align__(16) float d_xsum[(size_t)NCELLS * 32];
static __device__ double d_S0[144];
static __device__ double d_svf[12];
static __device__ double d_SA[1024];   // Σ x xᵀ        (32x32)
static __device__ double d_SB[1024];   // Σ sx mᵀ       (32x32)
static __device__ double d_SC[1024];   // Σ cnt m mᵀ    (32x32)
static __device__ double d_svx[32];    // Σ x
static __device__ double d_svm[32];    // Σ cnt m
static __device__ float  d_bn0[64];
static __device__ float  d_bn1[256];
static __device__ unsigned long long d_bsum[256];
static __device__ int    d_meta[2];    // [0]=V, [1]=Nvalid

__device__ __forceinline__ int3 coordsOf(float x, float y, float z) {
    int ix = (int)floorf(__fdiv_rn(x, 0.32f));
    int iy = (int)floorf(__fdiv_rn(__fadd_rn(y, 40.0f), 0.32f));
    int iz = (int)floorf(__fdiv_rn(__fadd_rn(z, 3.0f), 4.0f));
    return make_int3(ix, iy, iz);
}

__device__ __forceinline__ unsigned long long splat2(float v) {
    unsigned long long r;
    asm("mov.b64 %0, {%1, %1};" : "=l"(r) : "r"(__float_as_uint(v)));
    return r;
}
__device__ __forceinline__ unsigned long long pack2(float a, float b) {
    unsigned long long r;
    asm("mov.b64 %0, {%1, %2};" : "=l"(r) : "r"(__float_as_uint(a)), "r"(__float_as_uint(b)));
    return r;
}
__device__ __forceinline__ void unpack2(unsigned long long p, float& a, float& b) {
    unsigned int lo, hi;
    asm("mov.b64 {%0, %1}, %2;" : "=r"(lo), "=r"(hi) : "l"(p));
    a = __uint_as_float(lo); b = __uint_as_float(hi);
}
#define FMA2(acc, a, b) asm("fma.rn.f32x2 %0, %1, %2, %0;" : "+l"(acc) : "l"(a), "l"(b))

// -------------------- K0: zero --------------------
__global__ void k_zero() {
    int i = blockIdx.x * blockDim.x + threadIdx.x;
    if (i < NCELLS) {
        d_cnt[i] = 0; d_cursor[i] = 0;
        d_sums[i * 3 + 0] = 0.f; d_sums[i * 3 + 1] = 0.f; d_sums[i * 3 + 2] = 0.f;
    }
    if (i < 1024) { d_SA[i] = 0.0; d_SB[i] = 0.0; d_SC[i] = 0.0; }
    if (i < 144)  d_S0[i] = 0.0;
    if (i < 12)   d_svf[i] = 0.0;
    if (i < 32)   { d_svx[i] = 0.0; d_svm[i] = 0.0; }
}

// -------------------- K1: keys + histogram + xyz sums --------------------
__global__ void k_points(const float* __restrict__ pts, int n) {
    int i = blockIdx.x * blockDim.x + threadIdx.x;
    if (i >= n) return;
    const float* p = pts + (size_t)i * 5;
    float b = p[0], x = p[1], y = p[2], z = p[3];
    int3 c = coordsOf(x, y, z);
    int key = -1;
    if (c.x >= 0 && c.x < GX && c.y >= 0 && c.y < GY && c.z == 0) {
        key = (int)b * 55000 + c.x * 250 + c.y;
        if (key < 0 || key >= NCELLS) key = -1;
    }
    d_key[i] = key;
    if (key >= 0) {
        atomicAdd(&d_cnt[key], 1);
        atomicAdd(&d_sums[key * 3 + 0], x);
        atomicAdd(&d_sums[key * 3 + 1], y);
        atomicAdd(&d_sums[key * 3 + 2], z);
    }
}

// -------------------- K2: packed scans --------------------
__global__ void k_scan1() {
    __shared__ unsigned long long s[1024];
    int tid = threadIdx.x;
    int c = blockIdx.x * 1024 + tid;
    unsigned long long v = 0ULL;
    if (c < NCELLS) {
        int cn = d_cnt[c];
        v = ((unsigned long long)(cn > 0) << 32) | (unsigned int)cn;
    }
    s[tid] = v;
    __syncthreads();
    for (int o = 1; o < 1024; o <<= 1) {
        unsigned long long t = (tid >= o) ? s[tid - o] : 0ULL;
        __syncthreads();
        s[tid] += t;
        __syncthreads();
    }
    unsigned long long exc = s[tid] - v;
    if (c < NCELLS) {
        d_cellvid[c]   = (int)(exc >> 32);
        d_cellstart[c] = (int)(exc & 0xffffffffULL);
    }
    if (tid == 1023) d_bsum[blockIdx.x] = s[1023];
}

__global__ void k_scan2(int nb) {
    __shared__ unsigned long long s[256];
    int t = threadIdx.x;
    unsigned long long v = (t < nb) ? d_bsum[t] : 0ULL;
    s[t] = v;
    __syncthreads();
    for (int o = 1; o < 256; o <<= 1) {
        unsigned long long u = (t >= o) ? s[t - o] : 0ULL;
        __syncthreads();
        s[t] += u;
        __syncthreads();
    }
    if (t < nb) d_bsum[t] = s[t] - v;
    if (t == 255) {
        d_meta[0] = (int)(s[255] >> 32);
        d_meta[1] = (int)(s[255] & 0xffffffffULL);
    }
}

// -------------------- K3: finalize cells + coords output --------------------
__global__ void k_cells(float* __restrict__ out, int Vh) {
    int c = blockIdx.x * blockDim.x + threadIdx.x;
    if (c >= NCELLS) return;
    unsigned long long off = d_bsum[c >> 10];
    int vid = d_cellvid[c]   + (int)(off >> 32);
    int cst = d_cellstart[c] + (int)(off & 0xffffffffULL);
    d_cellvid[c] = vid;
    d_cellstart[c] = cst;
    int cn = d_cnt[c];
    if (cn > 0) {
        d_voxstart[vid] = cst;
        d_voxcnt[vid]   = cn;
        float fn = (float)cn;
        d_mean[vid * 3 + 0] = d_sums[c * 3 + 0] / fn;
        d_mean[vid * 3 + 1] = d_sums[c * 3 + 1] / fn;
        d_mean[vid * 3 + 2] = d_sums[c * 3 + 2] / fn;
        if (vid < Vh) {
            int b = c / 55000; int rem = c - b * 55000;
            int cx = rem / 250; int cy = rem - cx * 250;
            float* oc = out + (size_t)Vh * 128 + (size_t)vid * 4;
            oc[0] = (float)b; oc[1] = 0.f; oc[2] = (float)cy; oc[3] = (float)cx;
        }
    }
}

// -------------------- K4: counting-sort scatter --------------------
__global__ void k_scatter(int n) {
    int i = blockIdx.x * blockDim.x + threadIdx.x;
    if (i >= n) return;
    int k = d_key[i];
    if (k >= 0) {
        int pos = d_cellstart[k] + atomicAdd(&d_cursor[k], 1);
        d_ipos[i] = pos;
    } else {
        d_ipos[i] = -1;
    }
}

// -------------------- K5: compute 10 feats per point, store sorted (stride 12) -----
__global__ void k_l0feat(const float* __restrict__ pts, int n) {
    int i = blockIdx.x * blockDim.x + threadIdx.x;
    if (i >= n) return;
    int k = d_key[i];
    if (k < 0) return;
    const float* p = pts + (size_t)i * 5;
    float x = p[1], y = p[2], z = p[3], it = p[4];
    int3 c = coordsOf(x, y, z);
    int v = d_cellvid[k];
    const float XO = (float)(0.32 / 2 + 0.0);
    const float YO = (float)(0.32 / 2 - 40.0);
    const float ZO = (float)(4.0 / 2 - 3.0);
    float4 A = make_float4(x, y, z, it);
    float4 B = make_float4(x - d_mean[v * 3 + 0], y - d_mean[v * 3 + 1],
                           z - d_mean[v * 3 + 2], x - ((float)c.x * 0.32f + XO));
    float4 C = make_float4(y - ((float)c.y * 0.32f + YO), z - ZO, 0.f, 0.f);
    int pos = d_ipos[i];
    float4* dst = (float4*)(d_feat + (size_t)pos * 12);
    dst[0] = A; dst[1] = B; dst[2] = C;
}

// -------------------- K6: S0 = Σ feat featᵀ (12x12), svf = Σ feat ------------------
__global__ void k_statsS0() {
    __shared__ __align__(16) float fsm[384];
    int t = threadIdx.x;
    int N = d_meta[1];
    int N12 = N * 12;
    int nch = (N + 31) >> 5;
    int r = t / 12, c = t - r * 12;  // valid for t<144
    float acc = 0.f, sv = 0.f;
    for (int ch = blockIdx.x; ch < nch; ch += gridDim.x) {
        for (int j = t; j < 384; j += 256) {
            int idx = ch * 384 + j;
            fsm[j] = (idx < N12) ? d_feat[idx] : 0.f;
        }
        __syncthreads();
        if (t < 144) {
#pragma unroll 8
            for (int p = 0; p < 32; p++)
                acc = fmaf(fsm[p * 12 + r], fsm[p * 12 + c], acc);
        }
        if (t < 12) {
#pragma unroll 8
            for (int p = 0; p < 32; p++) sv += fsm[p * 12 + t];
        }
        __syncthreads();
    }
    if (t < 144) atomicAdd(&d_S0[r * 12 + c], (double)acc);
    if (t < 12)  atomicAdd(&d_svf[t], (double)sv);
}

// -------------------- K7: BN0 params from Gram matrix --------------------
__global__ void k_bnfin0(const float* __restrict__ g, const float* __restrict__ b,
                         const float* __restrict__ w0) {
    int c = threadIdx.x;
    if (c >= 32) return;
    float n = (float)d_meta[1];
    float sm = 0.f;
#pragma unroll
    for (int k = 0; k < 10; k++) sm = fmaf((float)d_svf[k], w0[k * 32 + c], sm);
    float mu = sm / n;
    float sq = 0.f;
    for (int i = 0; i < 10; i++) {
        float wi = w0[i * 32 + c];
        float row = 0.f;
        for (int j = 0; j < 10; j++)
            row = fmaf((float)d_S0[i * 12 + j], w0[j * 32 + c], row);
        sq = fmaf(wi, row, sq);
    }
    float var = sq / n - mu * mu;
    float istd = rsqrtf(var + 1e-3f);
    float sc = g[c] * istd;
    d_bn0[c] = sc;
    d_bn0[32 + c] = b[c] - mu * sc;
}

// -------------------- K8: layer0 apply (feats@w0, BN, ReLU) + xmax + xsum ----------
__global__ void __launch_bounds__(256) k_l0post(const float* __restrict__ w0) {
    __shared__ float fs[8][12];
    int t = threadIdx.x;
    int w = t >> 5, lane = t & 31;
    float wcol[10];
#pragma unroll
    for (int k = 0; k < 10; k++) wcol[k] = w0[k * 32 + lane];
    float sc = d_bn0[lane], sh = d_bn0[32 + lane];
    int V = d_meta[0];
    for (int v = blockIdx.x * 8 + w; v < V; v += gridDim.x * 8) {
        int st = d_voxstart[v], en = st + d_voxcnt[v];
        float m = 0.f, s = 0.f;
        for (int p = st; p < en; p++) {
            if (lane < 12) fs[w][lane] = d_feat[(size_t)p * 12 + lane];
            __syncwarp();
            float y = 0.f;
#pragma unroll
            for (int k = 0; k < 10; k++) y = fmaf(fs[w][k], wcol[k], y);
            __syncwarp();
            float x = fmaxf(fmaf(y, sc, sh), 0.f);
            d_x[(size_t)p * 32 + lane] = x;
            m = fmaxf(m, x); s += x;
        }
        d_xmax[(size_t)v * 32 + lane] = m;
        d_xsum[(size_t)v * 32 + lane] = s;
    }
}

// -------------------- K9: A = Σ x xᵀ over points --------------------
__global__ void __launch_bounds__(256) k_statsA() {
    __shared__ __align__(16) float xs[1024];
    int t = threadIdx.x;
    int N32 = d_meta[1] * 32;
    int nch = (d_meta[1] + 31) >> 5;
    int r = t >> 3, c4 = (t & 7) << 2;
    unsigned long long a01 = 0ULL, a23 = 0ULL;
    for (int ch = blockIdx.x; ch < nch; ch += gridDim.x) {
        int base = ch * 1024 + t * 4;
        float4 v = make_float4(0.f, 0.f, 0.f, 0.f);
        if (base < N32) v = *(const float4*)(d_x + base);
        *(float4*)&xs[t * 4] = v;
        __syncthreads();
#pragma unroll 8
        for (int p = 0; p < 32; p++) {
            unsigned long long xr2 = splat2(xs[p * 32 + r]);
            float4 xc = *(float4*)&xs[p * 32 + c4];
            unsigned long long c01 = pack2(xc.x, xc.y);
            unsigned long long c23 = pack2(xc.z, xc.w);
            FMA2(a01, xr2, c01);
            FMA2(a23, xr2, c23);
        }
        __syncthreads();
    }
    float f0, f1, f2, f3;
    unpack2(a01, f0, f1); unpack2(a23, f2, f3);
    atomicAdd(&d_SA[r * 32 + c4 + 0], (double)f0);
    atomicAdd(&d_SA[r * 32 + c4 + 1], (double)f1);
    atomicAdd(&d_SA[r * 32 + c4 + 2], (double)f2);
    atomicAdd(&d_SA[r * 32 + c4 + 3], (double)f3);
}

// -------------------- K10: B = Σ sx mᵀ, C = Σ cnt m mᵀ, svx, svm -------------------
__global__ void __launch_bounds__(256) k_statsBC() {
    __shared__ __align__(16) float ms[1024];
    __shared__ __align__(16) float sxs[1024];
    __shared__ float cnf[32];
    int t = threadIdx.x;
    int V = d_meta[0];
    int V32 = V * 32;
    int nch = (V + 31) >> 5;
    int r = t >> 3, c4 = (t & 7) << 2;
    unsigned long long B01 = 0, B23 = 0, C01 = 0, C23 = 0;
    float vx[4] = {0, 0, 0, 0}, vm[4] = {0, 0, 0, 0};
    for (int ch = blockIdx.x; ch < nch; ch += gridDim.x) {
        int base = ch * 1024 + t * 4;
        float4 mv = make_float4(0, 0, 0, 0), sv = make_float4(0, 0, 0, 0);
        if (base < V32) {
            mv = *(const float4*)(d_xmax + base);
            sv = *(const float4*)(d_xsum + base);
        }
        *(float4*)&ms[t * 4] = mv;
        *(float4*)&sxs[t * 4] = sv;
        if (t < 32) {
            int vv = ch * 32 + t;
            cnf[t] = (vv < V) ? (float)d_voxcnt[vv] : 0.f;
        }
        __syncthreads();
#pragma unroll 4
        for (int p = 0; p < 32; p++) {
            float cn = cnf[p];
            unsigned long long sxr2 = splat2(sxs[p * 32 + r]);
            unsigned long long cmr2 = splat2(cn * ms[p * 32 + r]);
            float4 m4 = *(float4*)&ms[p * 32 + c4];
            unsigned long long m01 = pack2(m4.x, m4.y);
            unsigned long long m23 = pack2(m4.z, m4.w);
            FMA2(B01, sxr2, m01); FMA2(B23, sxr2, m23);
            FMA2(C01, cmr2, m01); FMA2(C23, cmr2, m23);
            if (t < 8) {
                float4 sx4 = *(float4*)&sxs[p * 32 + c4];
                vx[0] += sx4.x; vx[1] += sx4.y; vx[2] += sx4.z; vx[3] += sx4.w;
                vm[0] = fmaf(cn, m4.x, vm[0]); vm[1] = fmaf(cn, m4.y, vm[1]);
                vm[2] = fmaf(cn, m4.z, vm[2]); vm[3] = fmaf(cn, m4.w, vm[3]);
            }
        }
        __syncthreads();
    }
    float b0, b1, b2, b3, c0, c1, c2, c3;
    unpack2(B01, b0, b1); unpack2(B23, b2, b3);
    unpack2(C01, c0, c1); unpack2(C23, c2, c3);
    atomicAdd(&d_SB[r * 32 + c4 + 0], (double)b0);
    atomicAdd(&d_SB[r * 32 + c4 + 1], (double)b1);
    atomicAdd(&d_SB[r * 32 + c4 + 2], (double)b2);
    atomicAdd(&d_SB[r * 32 + c4 + 3], (double)b3);
    atomicAdd(&d_SC[r * 32 + c4 + 0], (double)c0);
    atomicAdd(&d_SC[r * 32 + c4 + 1], (double)c1);
    atomicAdd(&d_SC[r * 32 + c4 + 2], (double)c2);
    atomicAdd(&d_SC[r * 32 + c4 + 3], (double)c3);
    if (t < 8) {
#pragma unroll
        for (int j = 0; j < 4; j++) {
            atomicAdd(&d_svx[c4 + j], (double)vx[j]);
            atomicAdd(&d_svm[c4 + j], (double)vm[j]);
        }
    }
}

// -------------------- K11: BN1 params — one block per channel --------------------
__device__ __forceinline__ float S64(int i, int j) {
    if (i < 32) {
        if (j < 32) return (float)d_SA[i * 32 + j];
        return (float)d_SB[i * 32 + (j - 32)];
    } else {
        if (j < 32) return (float)d_SB[j * 32 + (i - 32)];
        return (float)d_SC[(i - 32) * 32 + (j - 32)];
    }
}

__global__ void k_bnfin1(const float* __restrict__ w1, const float* __restrict__ g,
                         const float* __restrict__ b) {
    __shared__ float wc[64];
    __shared__ float red[64];
    int c = blockIdx.x;
    int i = threadIdx.x;  // 64 threads
    float wi = w1[i * 128 + c];
    wc[i] = wi;
    float sv = (i < 32) ? (float)d_svx[i] : (float)d_svm[i - 32];
    __syncthreads();
    float row = 0.f;
    for (int j = 0; j < 64; j++) row = fmaf(S64(i, j), wc[j], row);
    red[i] = fmaf(wi, row, 0.f) + 1e30f * 0.f;
    __shared__ float red2[64];
    red2[i] = sv * wi;
    __syncthreads();
    for (int o = 32; o > 0; o >>= 1) {
        if (i < o) { red[i] += red[i + o]; red2[i] += red2[i + o]; }
        __syncthreads();
    }
    if (i == 0) {
        float n = (float)d_meta[1];
        float mu = red2[0] / n;
        float var = red[0] / n - mu * mu;
        float istd = rsqrtf(var + 1e-3f);
        float sc = g[c] * istd;
        d_bn1[c] = sc;
        d_bn1[128 + c] = b[c] - mu * sc;
    }
}

// -------------------- K12: fused GEMM + BN1 + ReLU + pillar max --------------------
__global__ void __launch_bounds__(256) k_l1f(const float* __restrict__ w1,
                                             float* __restrict__ out, int Vh) {
    __shared__ __align__(16) float w1s[8192];          // 64x128
    __shared__ unsigned long long xpa[8][64];
    __shared__ unsigned long long xpb[8][64];
    for (int j = threadIdx.x; j < 2048; j += 256)
        ((float4*)w1s)[j] = ((const float4*)w1)[j];
    __syncthreads();
    int V = d_meta[0];
    int w = threadIdx.x >> 5, lane = threadIdx.x & 31;
    float4 scv = *(const float4*)(d_bn1 + 4 * lane);
    float4 shv = *(const float4*)(d_bn1 + 128 + 4 * lane);
    const float* wrow = w1s + 4 * lane;
    for (int v = blockIdx.x * 8 + w; v < V; v += gridDim.x * 8) {
        int st = d_voxstart[v], en = st + d_voxcnt[v];
        unsigned long long m2 = splat2(d_xmax[(size_t)v * 32 + lane]);
        xpa[w][32 + lane] = m2;
        xpb[w][32 + lane] = m2;
        float o0 = 0.f, o1 = 0.f, o2 = 0.f, o3 = 0.f;
        for (int p = st; p < en; p += 2) {
            int pB = (p + 1 < en) ? p + 1 : p;
            xpa[w][lane] = splat2(d_x[(size_t)p  * 32 + lane]);
            xpb[w][lane] = splat2(d_x[(size_t)pB * 32 + lane]);
            __syncwarp();
            unsigned long long A01 = 0, A23 = 0, B01 = 0, B23 = 0;
#pragma unroll 8
            for (int k = 0; k < 64; k++) {
                unsigned long long xa2 = xpa[w][k];
                unsigned long long xb2 = xpb[w][k];
                ulonglong2 wp = *(const ulonglong2*)(wrow + k * 128);
                FMA2(A01, xa2, wp.x);
                FMA2(A23, xa2, wp.y);
                FMA2(B01, xb2, wp.x);
                FMA2(B23, xb2, wp.y);
            }
            __syncwarp();
            float a0, a1, a2, a3, b0, b1, b2, b3;
            unpack2(A01, a0, a1); unpack2(A23, a2, a3);
            unpack2(B01, b0, b1); unpack2(B23, b2, b3);
            o0 = fmaxf(o0, fmaf(a0, scv.x, shv.x)); o0 = fmaxf(o0, fmaf(b0, scv.x, shv.x));
            o1 = fmaxf(o1, fmaf(a1, scv.y, shv.y)); o1 = fmaxf(o1, fmaf(b1, scv.y, shv.y));
            o2 = fmaxf(o2, fmaf(a2, scv.z, shv.z)); o2 = fmaxf(o2, fmaf(b2, scv.z, shv.z));
            o3 = fmaxf(o3, fmaf(a3, scv.w, shv.w)); o3 = fmaxf(o3, fmaf(b3, scv.w, shv.w));
        }
        if (v < Vh) {
            float4 r4 = make_float4(o0, o1, o2, o3);
            *(float4*)(out + (size_t)v * 128 + 4 * lane) = r4;
        }
    }
}

// -------------------- host --------------------
extern "C" void kernel_launch(void* const* d_in, const int* in_sizes, int n_in,
                              void* d_out, int out_size) {
    const float* pts = (const float*)d_in[0];
    const float* w0  = (const float*)d_in[1];
    const float* g0  = (const float*)d_in[2];
    const float* b0  = (const float*)d_in[3];
    const float* w1  = (const float*)d_in[4];
    const float* g1  = (const float*)d_in[5];
    const float* b1  = (const float*)d_in[6];
    float* out = (float*)d_out;

    int n = in_sizes[0] / 5;
    if (n > NMAX) n = NMAX;
    int Vh = out_size / 132;
    int nb = (NCELLS + 1023) / 1024;

    k_zero    <<<(NCELLS + 255) / 256, 256>>>();
    k_points  <<<(n + 255) / 256, 256>>>(pts, n);
    k_scan1   <<<nb, 1024>>>();
    k_scan2   <<<1, 256>>>(nb);
    k_cells   <<<(NCELLS + 255) / 256, 256>>>(out, Vh);
    k_scatter <<<(n + 255) / 256, 256>>>(n);
    k_l0feat  <<<(n + 255) / 256, 256>>>(pts, n);
    k_statsS0 <<<256, 256>>>();
    k_bnfin0  <<<1, 32>>>(g0, b0, w0);
    k_l0post  <<<1480, 256>>>(w0);
    k_statsA  <<<512, 256>>>();
    k_statsBC <<<256, 256>>>();
    k_bnfin1  <<<128, 64>>>(w1, g1, b1);
    k_l1f     <<<1480, 256>>>(w1, out, Vh);
}